// round 3
// baseline (speedup 1.0000x reference)
#include <cuda_runtime.h>
#include <math.h>
#include <stdint.h>

// Problem constants
#define Nn   2048
#define CIN  2
#define Hh   32
#define EMB  16
#define HOR  12
#define Bb   32
#define Tt   16
#define RW   1152   // g_R row width: 64 x-part (unused now) + 1024 h-part + 64 pad
#define KD   2048

// Device scratch
__device__ float g_A  [Nn * Nn];        // adjacency row-major (temp)
__device__ float g_At [Nn * Nn];        // adjacency transposed [k][m]
__device__ float g_R  [Nn * RW];        // RHS, k-major: [node][64 + b*32+h]
__device__ float g_G  [Nn * 1024];      // G_h = A @ H : [node][b*32+h]
__device__ float g_Bx [Nn * 1024];      // X all timesteps: [node][t*64 + b*2+c]
__device__ float g_Gx [Nn * 1024];      // A @ X_all      : [node][t*64 + b*2+c]
__device__ float g_C  [Nn * Bb * Hh];   // cell state
__device__ float g_Hf [Nn * Bb * Hh];   // fp32 h for projection

// ---------------------------------------------------------------------------
__device__ __forceinline__ float to_tf32(float x) {
    uint32_t u;
    asm("cvt.rna.tf32.f32 %0, %1;" : "=r"(u) : "f"(x));
    return __uint_as_float(u);
}
__device__ __forceinline__ float fsig(float x) { return 1.0f / (1.0f + __expf(-x)); }
__device__ __forceinline__ float ftanh(float x) { return 2.0f / (1.0f + __expf(-2.0f * x)) - 1.0f; }

__device__ __forceinline__ void cp16(float* dst, const float* src) {
    uint32_t s = (uint32_t)__cvta_generic_to_shared(dst);
    asm volatile("cp.async.cg.shared.global [%0], [%1], 16;" :: "r"(s), "l"(src));
}

__device__ __forceinline__ void mma_tf32(float (&d)[4], const uint32_t (&a)[4], const uint32_t (&b)[2]) {
    asm volatile(
        "mma.sync.aligned.m16n8k8.row.col.f32.tf32.tf32.f32 "
        "{%0,%1,%2,%3}, {%4,%5,%6,%7}, {%8,%9}, {%0,%1,%2,%3};"
        : "+f"(d[0]), "+f"(d[1]), "+f"(d[2]), "+f"(d[3])
        : "r"(a[0]), "r"(a[1]), "r"(a[2]), "r"(a[3]), "r"(b[0]), "r"(b[1]));
}

// ---------------------------------------------------------------------------
// A = softmax(relu(E1 @ E2^T)) row-major, values tf32-rounded
// ---------------------------------------------------------------------------
__global__ __launch_bounds__(256) void adj_kernel(const float* __restrict__ E1,
                                                  const float* __restrict__ E2) {
    int r = blockIdx.x;
    int tid = threadIdx.x;
    __shared__ float e1[EMB];
    __shared__ float red[256];
    if (tid < EMB) e1[tid] = E1[r * EMB + tid];
    __syncthreads();

    float v[8];
    float mx = -1e30f;
#pragma unroll
    for (int i = 0; i < 8; i++) {
        int c = tid + i * 256;
        float d = 0.f;
#pragma unroll
        for (int e = 0; e < EMB; e++) d += e1[e] * E2[c * EMB + e];
        d = fmaxf(d, 0.f);
        v[i] = d;
        mx = fmaxf(mx, d);
    }
    red[tid] = mx; __syncthreads();
    for (int s = 128; s > 0; s >>= 1) {
        if (tid < s) red[tid] = fmaxf(red[tid], red[tid + s]);
        __syncthreads();
    }
    mx = red[0]; __syncthreads();

    float sum = 0.f;
#pragma unroll
    for (int i = 0; i < 8; i++) { v[i] = expf(v[i] - mx); sum += v[i]; }
    red[tid] = sum; __syncthreads();
    for (int s = 128; s > 0; s >>= 1) {
        if (tid < s) red[tid] += red[tid + s];
        __syncthreads();
    }
    float inv = 1.0f / red[0];
#pragma unroll
    for (int i = 0; i < 8; i++) g_A[(size_t)r * Nn + tid + i * 256] = to_tf32(v[i] * inv);
}

// 32x32 tiled transpose: g_At[k][m] = g_A[m][k]
__global__ __launch_bounds__(256) void transpose_kernel() {
    __shared__ float t[32][33];
    int x = blockIdx.x * 32 + threadIdx.x;
    int y = blockIdx.y * 32 + threadIdx.y;
#pragma unroll
    for (int j = 0; j < 4; j++)
        t[threadIdx.y + 8 * j][threadIdx.x] = g_A[(size_t)(y + 8 * j) * Nn + x];
    __syncthreads();
    int x2 = blockIdx.y * 32 + threadIdx.x;
    int y2 = blockIdx.x * 32 + threadIdx.y;
#pragma unroll
    for (int j = 0; j < 4; j++)
        g_At[(size_t)(y2 + 8 * j) * Nn + x2] = t[threadIdx.x][threadIdx.y + 8 * j];
}

// ---------------------------------------------------------------------------
// g_Bx[n][t*64 + b*2 + c] = tf32(x[b][t][n][c])   (all timesteps at once)
// ---------------------------------------------------------------------------
__global__ __launch_bounds__(256) void buildx_kernel(const float* __restrict__ x) {
    int idx = blockIdx.x * 256 + threadIdx.x;  // n*1024 + q
    int n = idx >> 10;
    int q = idx & 1023;
    int t = q >> 6;
    int r6 = q & 63;
    int b = r6 >> 1;
    int c = r6 & 1;
    g_Bx[idx] = to_tf32(x[(((size_t)b * Tt + t) * Nn + n) * CIN + c]);
}

// ---------------------------------------------------------------------------
// Tensor-core GEMM (tf32): C[2048 x 1024] = A[2048 x 2048] @ B
//   At: [k][m] row-major (transposed A); B: [k][n] row-major (k = node)
// 128x128 block tile, BK=32, 256 threads (8 warps of 64x32), 3-stage cp.async
// ---------------------------------------------------------------------------
#define TSZ (32 * 136)          // one tile (A or B) in floats
#define SSTAGE (2 * TSZ)

__global__ void __launch_bounds__(256)
sgemm_tc(const float* __restrict__ At, const float* __restrict__ Bt, int ldB,
         float* __restrict__ C, int ldC) {
    extern __shared__ float smem[];
    int tid = threadIdx.x;
    int lane = tid & 31;
    int w = tid >> 5;
    int bm0 = blockIdx.y * 128;
    int bn0 = blockIdx.x * 128;
    int wm0 = (w >> 2) * 64;    // 2 warps along m
    int wn0 = (w & 3) * 32;     // 4 warps along n

    float acc[4][4][4];
#pragma unroll
    for (int mt = 0; mt < 4; mt++)
#pragma unroll
        for (int nt = 0; nt < 4; nt++)
#pragma unroll
            for (int i = 0; i < 4; i++) acc[mt][nt][i] = 0.f;

    auto load_stage = [&](int s, int k0) {
        float* sA = smem + s * SSTAGE;
        float* sB = sA + TSZ;
#pragma unroll
        for (int i = 0; i < 4; i++) {
            int ch = tid + i * 256;
            int r = ch >> 5;            // k row 0..31
            int c = (ch & 31) * 4;      // col 0..124
            cp16(sA + r * 136 + c, At + (size_t)(k0 + r) * Nn + bm0 + c);
        }
#pragma unroll
        for (int i = 0; i < 4; i++) {
            int ch = tid + i * 256;
            int r = ch >> 5;
            int c = (ch & 31) * 4;
            cp16(sB + r * 136 + c, Bt + (size_t)(k0 + r) * ldB + bn0 + c);
        }
    };

    load_stage(0, 0);
    asm volatile("cp.async.commit_group;" ::: "memory");
    load_stage(1, 32);
    asm volatile("cp.async.commit_group;" ::: "memory");

    const int NIT = KD / 32;  // 64
    for (int it = 0; it < NIT; ++it) {
        if (it + 2 < NIT) {
            asm volatile("cp.async.wait_group 1;" ::: "memory");
        } else {
            asm volatile("cp.async.wait_group 0;" ::: "memory");
        }
        __syncthreads();
        if (it + 2 < NIT) {
            load_stage((it + 2) % 3, (it + 2) * 32);
            asm volatile("cp.async.commit_group;" ::: "memory");
        }

        const float* sA = smem + (it % 3) * SSTAGE;
        const float* sB = sA + TSZ;
#pragma unroll
        for (int kk = 0; kk < 4; kk++) {
            uint32_t af[4][4];
#pragma unroll
            for (int mt = 0; mt < 4; mt++) {
                const float* pa = sA + (kk * 8 + (lane & 3)) * 136 + wm0 + mt * 16 + (lane >> 2);
                af[mt][0] = __float_as_uint(pa[0]);
                af[mt][1] = __float_as_uint(pa[8]);
                af[mt][2] = __float_as_uint(pa[4 * 136]);
                af[mt][3] = __float_as_uint(pa[4 * 136 + 8]);
            }
            uint32_t bf[4][2];
#pragma unroll
            for (int nt = 0; nt < 4; nt++) {
                const float* pb = sB + (kk * 8 + (lane & 3)) * 136 + wn0 + nt * 8 + (lane >> 2);
                bf[nt][0] = __float_as_uint(pb[0]);
                bf[nt][1] = __float_as_uint(pb[4 * 136]);
            }
#pragma unroll
            for (int mt = 0; mt < 4; mt++)
#pragma unroll
                for (int nt = 0; nt < 4; nt++) mma_tf32(acc[mt][nt], af[mt], bf[nt]);
        }
    }

#pragma unroll
    for (int mt = 0; mt < 4; mt++) {
        int r0 = bm0 + wm0 + mt * 16 + (lane >> 2);
#pragma unroll
        for (int nt = 0; nt < 4; nt++) {
            int c0 = bn0 + wn0 + nt * 8 + 2 * (lane & 3);
            *(float2*)&C[(size_t)r0 * ldC + c0] = make_float2(acc[mt][nt][0], acc[mt][nt][1]);
            *(float2*)&C[(size_t)(r0 + 8) * ldC + c0] = make_float2(acc[mt][nt][2], acc[mt][nt][3]);
        }
    }
}

// ---------------------------------------------------------------------------
// LSTM gates + state update. Warp handles 8 rows (2 groups of 4).
// h written COALESCED into g_R[node][64 + b*32 + lane].
// ---------------------------------------------------------------------------
__global__ __launch_bounds__(256) void lstm_kernel(const float* __restrict__ Wx,
                                                   const float* __restrict__ bx,
                                                   const float* __restrict__ Wh,
                                                   const float* __restrict__ bh,
                                                   int t) {
    __shared__ float4 Whs4[32 * 32];
    __shared__ float4 Wxs4[2 * 32];
    __shared__ float4 bs4[32];
    int tid = threadIdx.x;
    for (int i = tid; i < 1024; i += 256) {
        int k = i >> 5, l = i & 31;
        Whs4[i] = make_float4(Wh[k * 128 + l], Wh[k * 128 + 32 + l],
                              Wh[k * 128 + 64 + l], Wh[k * 128 + 96 + l]);
    }
    if (tid < 64) {
        int c = tid >> 5, l = tid & 31;
        Wxs4[tid] = make_float4(Wx[c * 128 + l], Wx[c * 128 + 32 + l],
                                Wx[c * 128 + 64 + l], Wx[c * 128 + 96 + l]);
    }
    if (tid < 32) {
        bs4[tid] = make_float4(bx[tid] + bh[tid], bx[32 + tid] + bh[32 + tid],
                               bx[64 + tid] + bh[64 + tid], bx[96 + tid] + bh[96 + tid]);
    }
    __syncthreads();

    int warp = tid >> 5, lane = tid & 31;
    int p0 = (blockIdx.x * 8 + warp) * 8;

#pragma unroll
    for (int grp = 0; grp < 2; grp++) {
        float4 acc[4];
        float ahv[4];
        int pn[4], pb[4];
#pragma unroll
        for (int r = 0; r < 4; r++) {
            int p = p0 + grp * 4 + r;
            int n = p >> 5;
            int b = p & 31;
            pn[r] = n; pb[r] = b;
            float ax0 = g_Gx[(size_t)n * 1024 + t * 64 + b * 2];
            float ax1 = g_Gx[(size_t)n * 1024 + t * 64 + b * 2 + 1];
            ahv[r] = g_G[(size_t)n * 1024 + b * 32 + lane];
            float4 a = bs4[lane];
            float4 w0 = Wxs4[lane];
            float4 w1 = Wxs4[32 + lane];
            a.x += ax0 * w0.x + ax1 * w1.x;
            a.y += ax0 * w0.y + ax1 * w1.y;
            a.z += ax0 * w0.z + ax1 * w1.z;
            a.w += ax0 * w0.w + ax1 * w1.w;
            acc[r] = a;
        }
#pragma unroll
        for (int k = 0; k < 32; k++) {
            float4 w = Whs4[k * 32 + lane];
#pragma unroll
            for (int r = 0; r < 4; r++) {
                float a = __shfl_sync(0xffffffffu, ahv[r], k);
                acc[r].x += a * w.x;
                acc[r].y += a * w.y;
                acc[r].z += a * w.z;
                acc[r].w += a * w.w;
            }
        }
#pragma unroll
        for (int r = 0; r < 4; r++) {
            float iv = fsig(acc[r].x);
            float fv = fsig(acc[r].y);
            float ov = fsig(acc[r].z);
            float gv = ftanh(acc[r].w);
            size_t cidx = (size_t)pn[r] * 1024 + pb[r] * 32 + lane;
            float c = g_C[cidx];
            float cn = fv * c + iv * gv;
            g_C[cidx] = cn;
            float h = ov * ftanh(cn);
            g_R[(size_t)pn[r] * RW + 64 + pb[r] * 32 + lane] = to_tf32(h);
            if (t == Tt - 1) g_Hf[cidx] = h;
        }
    }
}

// ---------------------------------------------------------------------------
// out[b, hz, n, 0] = sum_k h[b,n,k] * Wp[k,hz] + bp[hz]
// ---------------------------------------------------------------------------
__global__ __launch_bounds__(256) void proj_kernel(const float* __restrict__ Wp,
                                                   const float* __restrict__ bp,
                                                   float* __restrict__ out) {
    int idx = blockIdx.x * 256 + threadIdx.x;  // b*2048 + n
    int n = idx & (Nn - 1);
    int b = idx >> 11;
    float hv[32];
#pragma unroll
    for (int k = 0; k < 32; k++) hv[k] = g_Hf[(size_t)n * 1024 + b * 32 + k];
#pragma unroll
    for (int hz = 0; hz < HOR; hz++) {
        float s = bp[hz];
#pragma unroll
        for (int k = 0; k < 32; k++) s += hv[k] * Wp[k * HOR + hz];
        out[((size_t)b * HOR + hz) * Nn + n] = s;
    }
}

// ---------------------------------------------------------------------------
extern "C" void kernel_launch(void* const* d_in, const int* in_sizes, int n_in,
                              void* d_out, int out_size) {
    const float* x  = (const float*)d_in[0];
    const float* E1 = (const float*)d_in[1];
    const float* E2 = (const float*)d_in[2];
    const float* Wx = (const float*)d_in[3];
    const float* bx = (const float*)d_in[4];
    const float* Wh = (const float*)d_in[5];
    const float* bh = (const float*)d_in[6];
    const float* Wp = (const float*)d_in[7];
    const float* bp = (const float*)d_in[8];
    float* out = (float*)d_out;

    void *pR, *pC, *pAt, *pG, *pBx, *pGx;
    cudaGetSymbolAddress(&pR, g_R);
    cudaGetSymbolAddress(&pC, g_C);
    cudaGetSymbolAddress(&pAt, g_At);
    cudaGetSymbolAddress(&pG, g_G);
    cudaGetSymbolAddress(&pBx, g_Bx);
    cudaGetSymbolAddress(&pGx, g_Gx);

    static int smem_set = 0;
    if (!smem_set) {
        cudaFuncSetAttribute(sgemm_tc, cudaFuncAttributeMaxDynamicSharedMemorySize,
                             3 * SSTAGE * (int)sizeof(float));
        smem_set = 1;
    }

    cudaMemsetAsync(pR, 0, sizeof(float) * Nn * RW, 0);
    cudaMemsetAsync(pC, 0, sizeof(float) * Nn * Bb * Hh, 0);

    adj_kernel<<<Nn, 256>>>(E1, E2);
    transpose_kernel<<<dim3(64, 64), dim3(32, 8)>>>();
    buildx_kernel<<<(Nn * 1024) / 256, 256>>>(x);

    size_t gemmSmem = 3 * SSTAGE * sizeof(float);
    dim3 gemmGrid(1024 / 128, Nn / 128);  // (8, 16)

    // Gx = A @ X_all (once)
    sgemm_tc<<<gemmGrid, 256, gemmSmem>>>((const float*)pAt, (const float*)pBx, 1024,
                                          (float*)pGx, 1024);

    for (int t = 0; t < Tt; t++) {
        sgemm_tc<<<gemmGrid, 256, gemmSmem>>>((const float*)pAt, (const float*)pR + 64, RW,
                                              (float*)pG, 1024);
        lstm_kernel<<<(Nn * Bb) / 64, 256>>>(Wx, bx, Wh, bh, t);
    }

    proj_kernel<<<(Bb * Nn) / 256, 256>>>(Wp, bp, out);
}

// round 4
// speedup vs baseline: 1.2233x; 1.2233x over previous
#include <cuda_runtime.h>
#include <math.h>
#include <stdint.h>

// Problem constants
#define Nn   2048
#define CIN  2
#define Hh   32
#define EMB  16
#define HOR  12
#define Bb   32
#define Tt   16
#define RW   1152   // g_R row width: 64 unused + 1024 h-part + 64 pad
#define KD   2048
#define GSTRIDE (Nn * 1024)   // 2097152, one split-K half of G

// Device scratch
__device__ float g_A  [Nn * Nn];        // adjacency row-major (temp)
__device__ float g_At [Nn * Nn];        // adjacency transposed [k][m]
__device__ float g_R  [Nn * RW];        // GEMM RHS, k-major: [node][64 + b*32+h]
__device__ float g_G  [2 * GSTRIDE];    // split-K halves of A @ H (and temp for Gx)
__device__ float g_Bx [Nn * 1024];      // X all timesteps: [node][t*64 + b*2+c]
__device__ float g_Gx [Nn * 1024];      // A @ X_all (summed)
__device__ float g_C  [Nn * Bb * Hh];   // cell state, row-major [row=n*32+b][h]
__device__ float g_Hf [Nn * Bb * Hh];   // fp32 h for projection

// ---------------------------------------------------------------------------
__device__ __forceinline__ float to_tf32(float x) {
    uint32_t u;
    asm("cvt.rna.tf32.f32 %0, %1;" : "=r"(u) : "f"(x));
    return __uint_as_float(u);
}
__device__ __forceinline__ uint32_t to_tf32u(float x) {
    uint32_t u;
    asm("cvt.rna.tf32.f32 %0, %1;" : "=r"(u) : "f"(x));
    return u;
}
__device__ __forceinline__ float fsig(float x) { return 1.0f / (1.0f + __expf(-x)); }
__device__ __forceinline__ float ftanh(float x) { return 2.0f / (1.0f + __expf(-2.0f * x)) - 1.0f; }

__device__ __forceinline__ void cp16(float* dst, const float* src) {
    uint32_t s = (uint32_t)__cvta_generic_to_shared(dst);
    asm volatile("cp.async.cg.shared.global [%0], [%1], 16;" :: "r"(s), "l"(src));
}

__device__ __forceinline__ void mma_tf32(float (&d)[4], const uint32_t (&a)[4], const uint32_t (&b)[2]) {
    asm volatile(
        "mma.sync.aligned.m16n8k8.row.col.f32.tf32.tf32.f32 "
        "{%0,%1,%2,%3}, {%4,%5,%6,%7}, {%8,%9}, {%0,%1,%2,%3};"
        : "+f"(d[0]), "+f"(d[1]), "+f"(d[2]), "+f"(d[3])
        : "r"(a[0]), "r"(a[1]), "r"(a[2]), "r"(a[3]), "r"(b[0]), "r"(b[1]));
}

// ---------------------------------------------------------------------------
// A = softmax(relu(E1 @ E2^T)) row-major, tf32-rounded
// ---------------------------------------------------------------------------
__global__ __launch_bounds__(256) void adj_kernel(const float* __restrict__ E1,
                                                  const float* __restrict__ E2) {
    int r = blockIdx.x;
    int tid = threadIdx.x;
    __shared__ float e1[EMB];
    __shared__ float red[256];
    if (tid < EMB) e1[tid] = E1[r * EMB + tid];
    __syncthreads();

    float v[8];
    float mx = -1e30f;
#pragma unroll
    for (int i = 0; i < 8; i++) {
        int c = tid + i * 256;
        float d = 0.f;
#pragma unroll
        for (int e = 0; e < EMB; e++) d += e1[e] * E2[c * EMB + e];
        d = fmaxf(d, 0.f);
        v[i] = d;
        mx = fmaxf(mx, d);
    }
    red[tid] = mx; __syncthreads();
    for (int s = 128; s > 0; s >>= 1) {
        if (tid < s) red[tid] = fmaxf(red[tid], red[tid + s]);
        __syncthreads();
    }
    mx = red[0]; __syncthreads();

    float sum = 0.f;
#pragma unroll
    for (int i = 0; i < 8; i++) { v[i] = expf(v[i] - mx); sum += v[i]; }
    red[tid] = sum; __syncthreads();
    for (int s = 128; s > 0; s >>= 1) {
        if (tid < s) red[tid] += red[tid + s];
        __syncthreads();
    }
    float inv = 1.0f / red[0];
#pragma unroll
    for (int i = 0; i < 8; i++) g_A[(size_t)r * Nn + tid + i * 256] = to_tf32(v[i] * inv);
}

// 32x32 tiled transpose: g_At[k][m] = g_A[m][k]
__global__ __launch_bounds__(256) void transpose_kernel() {
    __shared__ float t[32][33];
    int x = blockIdx.x * 32 + threadIdx.x;
    int y = blockIdx.y * 32 + threadIdx.y;
#pragma unroll
    for (int j = 0; j < 4; j++)
        t[threadIdx.y + 8 * j][threadIdx.x] = g_A[(size_t)(y + 8 * j) * Nn + x];
    __syncthreads();
    int x2 = blockIdx.y * 32 + threadIdx.x;
    int y2 = blockIdx.x * 32 + threadIdx.y;
#pragma unroll
    for (int j = 0; j < 4; j++)
        g_At[(size_t)(y2 + 8 * j) * Nn + x2] = t[threadIdx.x][threadIdx.y + 8 * j];
}

// ---------------------------------------------------------------------------
// g_Bx[n][t*64 + b*2 + c] = tf32(x[b][t][n][c])
// ---------------------------------------------------------------------------
__global__ __launch_bounds__(256) void buildx_kernel(const float* __restrict__ x) {
    int idx = blockIdx.x * 256 + threadIdx.x;
    int n = idx >> 10;
    int q = idx & 1023;
    int t = q >> 6;
    int r6 = q & 63;
    int b = r6 >> 1;
    int c = r6 & 1;
    g_Bx[idx] = to_tf32(x[(((size_t)b * Tt + t) * Nn + n) * CIN + c]);
}

// g_Gx = g_G[0..] + g_G[GSTRIDE..]
__global__ __launch_bounds__(256) void addx_kernel() {
    int i = blockIdx.x * 256 + threadIdx.x;
    g_Gx[i] = g_G[i] + g_G[i + GSTRIDE];
}

// ---------------------------------------------------------------------------
// Split-K tensor-core GEMM (tf32): C_z[2048 x 1024] = A[:, z-half] @ B[z-half]
//   At: [k][m] row-major; Bt: [k][n] row-major (stride ldB)
// 128x128 block tile, BK=32, 128 threads (4 warps, 64x64 each), 3-stage cp.async
// blockIdx.z = split-K half; output to C + z*czStride
// ---------------------------------------------------------------------------
#define ASZ (32 * 136)
#define BSZ (32 * 136)
#define SSTAGE (ASZ + BSZ)
#define KSPLIT 1024

__global__ void __launch_bounds__(128, 2)
sgemm_tc(const float* __restrict__ At, const float* __restrict__ Bt, int ldB,
         float* __restrict__ C, int ldC, int czStride) {
    extern __shared__ float smem[];
    int tid = threadIdx.x;
    int lane = tid & 31;
    int w = tid >> 5;
    int bm0 = blockIdx.y * 128;
    int bn0 = blockIdx.x * 128;
    int kBase = blockIdx.z * KSPLIT;
    C += (size_t)blockIdx.z * czStride;
    int wm0 = (w & 1) * 64;
    int wn0 = (w >> 1) * 64;

    float acc[4][8][4];
#pragma unroll
    for (int mt = 0; mt < 4; mt++)
#pragma unroll
        for (int nt = 0; nt < 8; nt++)
#pragma unroll
            for (int i = 0; i < 4; i++) acc[mt][nt][i] = 0.f;

    auto load_stage = [&](int s, int k0) {
        float* sA = smem + s * SSTAGE;
        float* sB = sA + ASZ;
#pragma unroll
        for (int i = 0; i < 8; i++) {
            int ch = tid + i * 128;
            int r = ch >> 5;            // k row 0..31
            int c = (ch & 31) * 4;      // col 0..124
            cp16(sA + r * 136 + c, At + (size_t)(kBase + k0 + r) * Nn + bm0 + c);
        }
#pragma unroll
        for (int i = 0; i < 8; i++) {
            int ch = tid + i * 128;
            int r = ch >> 5;
            int c = (ch & 31) * 4;
            cp16(sB + r * 136 + c, Bt + (size_t)(kBase + k0 + r) * ldB + bn0 + c);
        }
    };

    load_stage(0, 0);
    asm volatile("cp.async.commit_group;" ::: "memory");
    load_stage(1, 32);
    asm volatile("cp.async.commit_group;" ::: "memory");

    const int NIT = KSPLIT / 32;  // 32
    for (int it = 0; it < NIT; ++it) {
        if (it + 2 < NIT) {
            asm volatile("cp.async.wait_group 1;" ::: "memory");
        } else {
            asm volatile("cp.async.wait_group 0;" ::: "memory");
        }
        __syncthreads();
        if (it + 2 < NIT) {
            load_stage((it + 2) % 3, (it + 2) * 32);
            asm volatile("cp.async.commit_group;" ::: "memory");
        }

        const float* sA = smem + (it % 3) * SSTAGE;
        const float* sB = sA + ASZ;
#pragma unroll
        for (int kk = 0; kk < 4; kk++) {
            uint32_t af[4][4];
#pragma unroll
            for (int mt = 0; mt < 4; mt++) {
                const float* pa = sA + (kk * 8 + (lane & 3)) * 136 + wm0 + mt * 16 + (lane >> 2);
                af[mt][0] = __float_as_uint(pa[0]);
                af[mt][1] = __float_as_uint(pa[8]);
                af[mt][2] = __float_as_uint(pa[4 * 136]);
                af[mt][3] = __float_as_uint(pa[4 * 136 + 8]);
            }
            uint32_t bf[8][2];
#pragma unroll
            for (int nt = 0; nt < 8; nt++) {
                const float* pb = sB + (kk * 8 + (lane & 3)) * 136 + wn0 + nt * 8 + (lane >> 2);
                bf[nt][0] = __float_as_uint(pb[0]);
                bf[nt][1] = __float_as_uint(pb[4 * 136]);
            }
#pragma unroll
            for (int mt = 0; mt < 4; mt++)
#pragma unroll
                for (int nt = 0; nt < 8; nt++) mma_tf32(acc[mt][nt], af[mt], bf[nt]);
        }
    }

#pragma unroll
    for (int mt = 0; mt < 4; mt++) {
        int r0 = bm0 + wm0 + mt * 16 + (lane >> 2);
#pragma unroll
        for (int nt = 0; nt < 8; nt++) {
            int c0 = bn0 + wn0 + nt * 8 + 2 * (lane & 3);
            *(float2*)&C[(size_t)r0 * ldC + c0] = make_float2(acc[mt][nt][0], acc[mt][nt][1]);
            *(float2*)&C[(size_t)(r0 + 8) * ldC + c0] = make_float2(acc[mt][nt][2], acc[mt][nt][3]);
        }
    }
}

// ---------------------------------------------------------------------------
// Tensor-core LSTM: gates[65536 x 128] = H[65536 x 32] @ W[32 x 128]
//   H[row][k] = G0[row*32+k] + G1[row*32+k]   (row = n*32 + b)
// 256 threads / 8 warps; warp = 16 rows x 128 gate-cols (16 m16n8k8 n-tiles).
// Epilogue adds x-part (Gx @ Wx) + bias, does pointwise LSTM, writes h/c.
// ---------------------------------------------------------------------------
__global__ __launch_bounds__(256) void lstm_tc(const float* __restrict__ Wx,
                                               const float* __restrict__ bx,
                                               const float* __restrict__ Wh,
                                               const float* __restrict__ bh,
                                               int t) {
    __shared__ float Whs[32 * 136];
    __shared__ float Wx0[128], Wx1[128], bsum[128];
    int tid = threadIdx.x;
    for (int i = tid; i < 4096; i += 256) {
        int k = i >> 7, g = i & 127;
        Whs[k * 136 + g] = to_tf32(Wh[i]);
    }
    if (tid < 128) {
        Wx0[tid] = Wx[tid];
        Wx1[tid] = Wx[128 + tid];
        bsum[tid] = bx[tid] + bh[tid];
    }
    __syncthreads();

    int lane = tid & 31, warp = tid >> 5;
    int rowbase = blockIdx.x * 128 + warp * 16;
    int r_lo = rowbase + (lane >> 2);

    float acc[16][4];
#pragma unroll
    for (int nt = 0; nt < 16; nt++)
#pragma unroll
        for (int i = 0; i < 4; i++) acc[nt][i] = 0.f;

    const float* G0 = g_G;
    const float* G1 = g_G + GSTRIDE;

#pragma unroll
    for (int kk = 0; kk < 4; kk++) {
        int k0 = kk * 8 + (lane & 3);
        size_t lo = (size_t)r_lo * 32 + k0;
        size_t hi = lo + 8 * 32;
        uint32_t a[4];
        a[0] = to_tf32u(G0[lo] + G1[lo]);
        a[1] = to_tf32u(G0[hi] + G1[hi]);
        a[2] = to_tf32u(G0[lo + 4] + G1[lo + 4]);
        a[3] = to_tf32u(G0[hi + 4] + G1[hi + 4]);
#pragma unroll
        for (int nt = 0; nt < 16; nt++) {
            const float* pb = &Whs[k0 * 136 + nt * 8 + (lane >> 2)];
            uint32_t b[2];
            b[0] = __float_as_uint(pb[0]);
            b[1] = __float_as_uint(pb[4 * 136]);
            mma_tf32(acc[nt], a, b);
        }
    }

    // epilogue: x-part + bias + pointwise LSTM
    int cole = 2 * (lane & 3);
#pragma unroll
    for (int rs = 0; rs < 2; rs++) {
        int r = r_lo + rs * 8;
        int n = r >> 5, b = r & 31;
        float ax0 = g_Gx[(size_t)n * 1024 + t * 64 + b * 2];
        float ax1 = g_Gx[(size_t)n * 1024 + t * 64 + b * 2 + 1];
#pragma unroll
        for (int j = 0; j < 4; j++) {
            int col = j * 8 + cole;   // h-unit index (even), pair (col, col+1)
            float gi0 = acc[j][rs * 2]      + ax0 * Wx0[col]      + ax1 * Wx1[col]      + bsum[col];
            float gi1 = acc[j][rs * 2 + 1]  + ax0 * Wx0[col + 1]  + ax1 * Wx1[col + 1]  + bsum[col + 1];
            float gf0 = acc[j + 4][rs * 2]     + ax0 * Wx0[32 + col]     + ax1 * Wx1[32 + col]     + bsum[32 + col];
            float gf1 = acc[j + 4][rs * 2 + 1] + ax0 * Wx0[32 + col + 1] + ax1 * Wx1[32 + col + 1] + bsum[32 + col + 1];
            float go0 = acc[j + 8][rs * 2]     + ax0 * Wx0[64 + col]     + ax1 * Wx1[64 + col]     + bsum[64 + col];
            float go1 = acc[j + 8][rs * 2 + 1] + ax0 * Wx0[64 + col + 1] + ax1 * Wx1[64 + col + 1] + bsum[64 + col + 1];
            float gg0 = acc[j + 12][rs * 2]     + ax0 * Wx0[96 + col]     + ax1 * Wx1[96 + col]     + bsum[96 + col];
            float gg1 = acc[j + 12][rs * 2 + 1] + ax0 * Wx0[96 + col + 1] + ax1 * Wx1[96 + col + 1] + bsum[96 + col + 1];

            float iv0 = fsig(gi0), iv1 = fsig(gi1);
            float fv0 = fsig(gf0), fv1 = fsig(gf1);
            float ov0 = fsig(go0), ov1 = fsig(go1);
            float gv0 = ftanh(gg0), gv1 = ftanh(gg1);

            size_t ci = (size_t)r * 32 + col;
            float2 cold = *(const float2*)&g_C[ci];
            float cn0 = fv0 * cold.x + iv0 * gv0;
            float cn1 = fv1 * cold.y + iv1 * gv1;
            *(float2*)&g_C[ci] = make_float2(cn0, cn1);
            float h0 = ov0 * ftanh(cn0);
            float h1 = ov1 * ftanh(cn1);
            *(float2*)&g_R[(size_t)n * RW + 64 + b * 32 + col] =
                make_float2(to_tf32(h0), to_tf32(h1));
            if (t == Tt - 1) *(float2*)&g_Hf[ci] = make_float2(h0, h1);
        }
    }
}

// ---------------------------------------------------------------------------
// out[b, hz, n, 0] = sum_k h[b,n,k] * Wp[k,hz] + bp[hz]
// ---------------------------------------------------------------------------
__global__ __launch_bounds__(256) void proj_kernel(const float* __restrict__ Wp,
                                                   const float* __restrict__ bp,
                                                   float* __restrict__ out) {
    int idx = blockIdx.x * 256 + threadIdx.x;  // b*2048 + n
    int n = idx & (Nn - 1);
    int b = idx >> 11;
    float hv[32];
#pragma unroll
    for (int k = 0; k < 32; k++) hv[k] = g_Hf[(size_t)n * 1024 + b * 32 + k];
#pragma unroll
    for (int hz = 0; hz < HOR; hz++) {
        float s = bp[hz];
#pragma unroll
        for (int k = 0; k < 32; k++) s += hv[k] * Wp[k * HOR + hz];
        out[((size_t)b * HOR + hz) * Nn + n] = s;
    }
}

// ---------------------------------------------------------------------------
extern "C" void kernel_launch(void* const* d_in, const int* in_sizes, int n_in,
                              void* d_out, int out_size) {
    const float* x  = (const float*)d_in[0];
    const float* E1 = (const float*)d_in[1];
    const float* E2 = (const float*)d_in[2];
    const float* Wx = (const float*)d_in[3];
    const float* bx = (const float*)d_in[4];
    const float* Wh = (const float*)d_in[5];
    const float* bh = (const float*)d_in[6];
    const float* Wp = (const float*)d_in[7];
    const float* bp = (const float*)d_in[8];
    float* out = (float*)d_out;

    void *pR, *pC, *pAt, *pG, *pBx;
    cudaGetSymbolAddress(&pR, g_R);
    cudaGetSymbolAddress(&pC, g_C);
    cudaGetSymbolAddress(&pAt, g_At);
    cudaGetSymbolAddress(&pG, g_G);
    cudaGetSymbolAddress(&pBx, g_Bx);

    static int smem_set = 0;
    if (!smem_set) {
        cudaFuncSetAttribute(sgemm_tc, cudaFuncAttributeMaxDynamicSharedMemorySize,
                             3 * SSTAGE * (int)sizeof(float));
        smem_set = 1;
    }

    cudaMemsetAsync(pR, 0, sizeof(float) * Nn * RW, 0);
    cudaMemsetAsync(pC, 0, sizeof(float) * Nn * Bb * Hh, 0);

    adj_kernel<<<Nn, 256>>>(E1, E2);
    transpose_kernel<<<dim3(64, 64), dim3(32, 8)>>>();
    buildx_kernel<<<(Nn * 1024) / 256, 256>>>(x);

    size_t gemmSmem = 3 * SSTAGE * sizeof(float);
    dim3 gemmGrid(1024 / 128, Nn / 128, 2);  // (8, 16, 2) = 256 CTAs

    // Gx = A @ X_all (split halves into g_G, then summed into g_Gx)
    sgemm_tc<<<gemmGrid, 128, gemmSmem>>>((const float*)pAt, (const float*)pBx, 1024,
                                          (float*)pG, 1024, GSTRIDE);
    addx_kernel<<<GSTRIDE / 256, 256>>>();

    for (int t = 0; t < Tt; t++) {
        sgemm_tc<<<gemmGrid, 128, gemmSmem>>>((const float*)pAt, (const float*)pR + 64, RW,
                                              (float*)pG, 1024, GSTRIDE);
        lstm_tc<<<(Nn * Bb) / 128, 256>>>(Wx, bx, Wh, bh, t);
    }

    proj_kernel<<<(Bb * Nn) / 256, 256>>>(Wp, bp, out);
}

// round 5
// speedup vs baseline: 1.6752x; 1.3694x over previous
#include <cuda_runtime.h>
#include <cuda_fp16.h>
#include <math.h>
#include <stdint.h>

// Problem constants
#define Nn   2048
#define CIN  2
#define Hh   32
#define EMB  16
#define HOR  12
#define Bb   32
#define Tt   16
#define KD   2048
#define GSTRIDE (Nn * 1024)

// Device scratch
__device__ __half g_Ah [Nn * Nn];       // adjacency fp16, [m][k] row-major
__device__ __half g_Rh [Nn * 1024];     // H fp16, [node(k)][b*32+h(n)]
__device__ __half g_Bxh[Nn * 1024];     // X all timesteps fp16: [node][t*64+b*2+c]
__device__ float  g_G  [2 * GSTRIDE];   // split-K halves of A @ H
__device__ float  g_Gx [Nn * 1024];     // A @ X_all (summed)
__device__ float  g_C  [Nn * Bb * Hh];  // cell state [row=n*32+b][h]
__device__ float  g_Hf [Nn * Bb * Hh];  // fp32 h for projection

// ---------------------------------------------------------------------------
__device__ __forceinline__ float to_tf32(float x) {
    uint32_t u;
    asm("cvt.rna.tf32.f32 %0, %1;" : "=r"(u) : "f"(x));
    return __uint_as_float(u);
}
__device__ __forceinline__ uint32_t to_tf32u(float x) {
    uint32_t u;
    asm("cvt.rna.tf32.f32 %0, %1;" : "=r"(u) : "f"(x));
    return u;
}
__device__ __forceinline__ float fsig(float x) { return 1.0f / (1.0f + __expf(-x)); }
__device__ __forceinline__ float ftanh(float x) { return 2.0f / (1.0f + __expf(-2.0f * x)) - 1.0f; }

__device__ __forceinline__ void cp16(void* dst, const void* src) {
    uint32_t s = (uint32_t)__cvta_generic_to_shared(dst);
    asm volatile("cp.async.cg.shared.global [%0], [%1], 16;" :: "r"(s), "l"(src));
}

__device__ __forceinline__ void ldsm_x4(uint32_t (&r)[4], const void* p) {
    uint32_t a = (uint32_t)__cvta_generic_to_shared(p);
    asm volatile("ldmatrix.sync.aligned.m8n8.x4.shared.b16 {%0,%1,%2,%3}, [%4];"
                 : "=r"(r[0]), "=r"(r[1]), "=r"(r[2]), "=r"(r[3]) : "r"(a));
}
__device__ __forceinline__ void ldsm_x4_t(uint32_t (&r)[4], const void* p) {
    uint32_t a = (uint32_t)__cvta_generic_to_shared(p);
    asm volatile("ldmatrix.sync.aligned.m8n8.x4.trans.shared.b16 {%0,%1,%2,%3}, [%4];"
                 : "=r"(r[0]), "=r"(r[1]), "=r"(r[2]), "=r"(r[3]) : "r"(a));
}

__device__ __forceinline__ void mma_fp16(float (&d)[4], const uint32_t (&a)[4], const uint32_t* b) {
    asm volatile(
        "mma.sync.aligned.m16n8k16.row.col.f32.f16.f16.f32 "
        "{%0,%1,%2,%3}, {%4,%5,%6,%7}, {%8,%9}, {%0,%1,%2,%3};"
        : "+f"(d[0]), "+f"(d[1]), "+f"(d[2]), "+f"(d[3])
        : "r"(a[0]), "r"(a[1]), "r"(a[2]), "r"(a[3]), "r"(b[0]), "r"(b[1]));
}

__device__ __forceinline__ void mma_tf32(float (&d)[4], const uint32_t (&a)[4], const uint32_t (&b)[2]) {
    asm volatile(
        "mma.sync.aligned.m16n8k8.row.col.f32.tf32.tf32.f32 "
        "{%0,%1,%2,%3}, {%4,%5,%6,%7}, {%8,%9}, {%0,%1,%2,%3};"
        : "+f"(d[0]), "+f"(d[1]), "+f"(d[2]), "+f"(d[3])
        : "r"(a[0]), "r"(a[1]), "r"(a[2]), "r"(a[3]), "r"(b[0]), "r"(b[1]));
}

// ---------------------------------------------------------------------------
// A = softmax(relu(E1 @ E2^T)) row-major [m][k], written as fp16
// ---------------------------------------------------------------------------
__global__ __launch_bounds__(256) void adj_kernel(const float* __restrict__ E1,
                                                  const float* __restrict__ E2) {
    int r = blockIdx.x;
    int tid = threadIdx.x;
    __shared__ float e1[EMB];
    __shared__ float red[256];
    if (tid < EMB) e1[tid] = E1[r * EMB + tid];
    __syncthreads();

    float v[8];
    float mx = -1e30f;
#pragma unroll
    for (int i = 0; i < 8; i++) {
        int c = tid + i * 256;
        float d = 0.f;
#pragma unroll
        for (int e = 0; e < EMB; e++) d += e1[e] * E2[c * EMB + e];
        d = fmaxf(d, 0.f);
        v[i] = d;
        mx = fmaxf(mx, d);
    }
    red[tid] = mx; __syncthreads();
    for (int s = 128; s > 0; s >>= 1) {
        if (tid < s) red[tid] = fmaxf(red[tid], red[tid + s]);
        __syncthreads();
    }
    mx = red[0]; __syncthreads();

    float sum = 0.f;
#pragma unroll
    for (int i = 0; i < 8; i++) { v[i] = expf(v[i] - mx); sum += v[i]; }
    red[tid] = sum; __syncthreads();
    for (int s = 128; s > 0; s >>= 1) {
        if (tid < s) red[tid] += red[tid + s];
        __syncthreads();
    }
    float inv = 1.0f / red[0];
#pragma unroll
    for (int i = 0; i < 8; i++)
        g_Ah[(size_t)r * Nn + tid + i * 256] = __float2half_rn(v[i] * inv);
}

// ---------------------------------------------------------------------------
// g_Bxh[n][t*64 + b*2 + c] = fp16(x[b][t][n][c])
// ---------------------------------------------------------------------------
__global__ __launch_bounds__(256) void buildx_kernel(const float* __restrict__ x) {
    int idx = blockIdx.x * 256 + threadIdx.x;
    int n = idx >> 10;
    int q = idx & 1023;
    int t = q >> 6;
    int r6 = q & 63;
    int b = r6 >> 1;
    int c = r6 & 1;
    g_Bxh[idx] = __float2half_rn(x[(((size_t)b * Tt + t) * Nn + n) * CIN + c]);
}

// g_Gx = g_G[0..] + g_G[GSTRIDE..]
__global__ __launch_bounds__(256) void addx_kernel() {
    int i = blockIdx.x * 256 + threadIdx.x;
    g_Gx[i] = g_G[i] + g_G[i + GSTRIDE];
}

// ---------------------------------------------------------------------------
// fp16 tensor-core GEMM, split-K: C_z[2048 x 1024] = A[:, z-half] @ B[z-half]
//   Ah: [m][k] row-major fp16; Bh: [k][n] row-major fp16 (ld 1024)
// 128x128 tile, BK=32, 128 threads (4 warps of 64x64), 3-stage cp.async,
// ldmatrix fragment loads, m16n8k16 mma, fp32 accum.
// ---------------------------------------------------------------------------
#define APITCH 40            // halves per m-row (32 + 8 skew) = 80B
#define BPITCH 136           // halves per k-row (128 + 8 skew) = 272B
#define ASZH (128 * APITCH)  // 5120 halves
#define BSZH (32 * BPITCH)   // 4352 halves
#define SSTAGEH (ASZH + BSZH)  // 9472 halves = 18944 B
#define KSPLIT 1024

__global__ void __launch_bounds__(128, 2)
sgemm_fp16(const __half* __restrict__ Ah, const __half* __restrict__ Bh,
           float* __restrict__ C, int czStride) {
    extern __shared__ __half smem[];
    int tid = threadIdx.x;
    int lane = tid & 31;
    int w = tid >> 5;
    int bm0 = blockIdx.y * 128;
    int bn0 = blockIdx.x * 128;
    int kBase = blockIdx.z * KSPLIT;
    C += (size_t)blockIdx.z * czStride;
    int wm0 = (w & 1) * 64;
    int wn0 = (w >> 1) * 64;

    float acc[4][8][4];
#pragma unroll
    for (int mt = 0; mt < 4; mt++)
#pragma unroll
        for (int nt = 0; nt < 8; nt++)
#pragma unroll
            for (int i = 0; i < 4; i++) acc[mt][nt][i] = 0.f;

    auto load_stage = [&](int s, int k0) {
        __half* sA = smem + s * SSTAGEH;
        __half* sB = sA + ASZH;
        // A tile: 128 m-rows x 32 k halves = 512 chunks of 16B
#pragma unroll
        for (int i = 0; i < 4; i++) {
            int ch = tid + i * 128;
            int r = ch >> 2;             // m row 0..127
            int c = ch & 3;              // 16B chunk (8 halves)
            cp16(sA + r * APITCH + c * 8,
                 Ah + (size_t)(bm0 + r) * KD + kBase + k0 + c * 8);
        }
        // B tile: 32 k-rows x 128 n halves = 512 chunks
#pragma unroll
        for (int i = 0; i < 4; i++) {
            int ch = tid + i * 128;
            int r = ch >> 4;             // k row 0..31
            int c = ch & 15;             // 16B chunk
            cp16(sB + r * BPITCH + c * 8,
                 Bh + (size_t)(kBase + k0 + r) * 1024 + bn0 + c * 8);
        }
    };

    load_stage(0, 0);
    asm volatile("cp.async.commit_group;" ::: "memory");
    load_stage(1, 32);
    asm volatile("cp.async.commit_group;" ::: "memory");

    const int NIT = KSPLIT / 32;  // 32
    for (int it = 0; it < NIT; ++it) {
        if (it + 2 < NIT) {
            asm volatile("cp.async.wait_group 1;" ::: "memory");
        } else {
            asm volatile("cp.async.wait_group 0;" ::: "memory");
        }
        __syncthreads();
        if (it + 2 < NIT) {
            load_stage((it + 2) % 3, (it + 2) * 32);
            asm volatile("cp.async.commit_group;" ::: "memory");
        }

        const __half* sA = smem + (it % 3) * SSTAGEH;
        const __half* sB = sA + ASZH;
#pragma unroll
        for (int kk = 0; kk < 2; kk++) {
            uint32_t a[4][4];
#pragma unroll
            for (int mt = 0; mt < 4; mt++) {
                ldsm_x4(a[mt], sA + (wm0 + mt * 16 + (lane & 15)) * APITCH
                               + kk * 16 + ((lane >> 4) << 3));
            }
            uint32_t b[8][2];
#pragma unroll
            for (int np = 0; np < 4; np++) {
                uint32_t t4[4];
                ldsm_x4_t(t4, sB + (kk * 16 + (lane & 15)) * BPITCH
                              + wn0 + np * 16 + ((lane >> 4) << 3));
                b[np * 2][0] = t4[0]; b[np * 2][1] = t4[1];
                b[np * 2 + 1][0] = t4[2]; b[np * 2 + 1][1] = t4[3];
            }
#pragma unroll
            for (int mt = 0; mt < 4; mt++)
#pragma unroll
                for (int nt = 0; nt < 8; nt++) mma_fp16(acc[mt][nt], a[mt], b[nt]);
        }
    }

#pragma unroll
    for (int mt = 0; mt < 4; mt++) {
        int r0 = bm0 + wm0 + mt * 16 + (lane >> 2);
#pragma unroll
        for (int nt = 0; nt < 8; nt++) {
            int c0 = bn0 + wn0 + nt * 8 + 2 * (lane & 3);
            *(float2*)&C[(size_t)r0 * 1024 + c0] = make_float2(acc[mt][nt][0], acc[mt][nt][1]);
            *(float2*)&C[(size_t)(r0 + 8) * 1024 + c0] = make_float2(acc[mt][nt][2], acc[mt][nt][3]);
        }
    }
}

// ---------------------------------------------------------------------------
// Tensor-core LSTM: gates[65536 x 128] = (G0+G1)[65536 x 32] @ Wh[32 x 128]
// (tf32 mma — G is fp32). Epilogue: x-part + bias + pointwise; h -> fp16 g_Rh.
// ---------------------------------------------------------------------------
__global__ __launch_bounds__(256) void lstm_tc(const float* __restrict__ Wx,
                                               const float* __restrict__ bx,
                                               const float* __restrict__ Wh,
                                               const float* __restrict__ bh,
                                               int t) {
    __shared__ float Whs[32 * 136];
    __shared__ float Wx0[128], Wx1[128], bsum[128];
    int tid = threadIdx.x;
    for (int i = tid; i < 4096; i += 256) {
        int k = i >> 7, g = i & 127;
        Whs[k * 136 + g] = to_tf32(Wh[i]);
    }
    if (tid < 128) {
        Wx0[tid] = Wx[tid];
        Wx1[tid] = Wx[128 + tid];
        bsum[tid] = bx[tid] + bh[tid];
    }
    __syncthreads();

    int lane = tid & 31, warp = tid >> 5;
    int rowbase = blockIdx.x * 128 + warp * 16;
    int r_lo = rowbase + (lane >> 2);

    float acc[16][4];
#pragma unroll
    for (int nt = 0; nt < 16; nt++)
#pragma unroll
        for (int i = 0; i < 4; i++) acc[nt][i] = 0.f;

    const float* G0 = g_G;
    const float* G1 = g_G + GSTRIDE;

#pragma unroll
    for (int kk = 0; kk < 4; kk++) {
        int k0 = kk * 8 + (lane & 3);
        size_t lo = (size_t)r_lo * 32 + k0;
        size_t hi = lo + 8 * 32;
        uint32_t a[4];
        a[0] = to_tf32u(G0[lo] + G1[lo]);
        a[1] = to_tf32u(G0[hi] + G1[hi]);
        a[2] = to_tf32u(G0[lo + 4] + G1[lo + 4]);
        a[3] = to_tf32u(G0[hi + 4] + G1[hi + 4]);
#pragma unroll
        for (int nt = 0; nt < 16; nt++) {
            const float* pb = &Whs[k0 * 136 + nt * 8 + (lane >> 2)];
            uint32_t b[2];
            b[0] = __float_as_uint(pb[0]);
            b[1] = __float_as_uint(pb[4 * 136]);
            mma_tf32(acc[nt], a, b);
        }
    }

    int cole = 2 * (lane & 3);
#pragma unroll
    for (int rs = 0; rs < 2; rs++) {
        int r = r_lo + rs * 8;
        int n = r >> 5, b = r & 31;
        float ax0 = g_Gx[(size_t)n * 1024 + t * 64 + b * 2];
        float ax1 = g_Gx[(size_t)n * 1024 + t * 64 + b * 2 + 1];
#pragma unroll
        for (int j = 0; j < 4; j++) {
            int col = j * 8 + cole;
            float gi0 = acc[j][rs * 2]      + ax0 * Wx0[col]      + ax1 * Wx1[col]      + bsum[col];
            float gi1 = acc[j][rs * 2 + 1]  + ax0 * Wx0[col + 1]  + ax1 * Wx1[col + 1]  + bsum[col + 1];
            float gf0 = acc[j + 4][rs * 2]     + ax0 * Wx0[32 + col]     + ax1 * Wx1[32 + col]     + bsum[32 + col];
            float gf1 = acc[j + 4][rs * 2 + 1] + ax0 * Wx0[32 + col + 1] + ax1 * Wx1[32 + col + 1] + bsum[32 + col + 1];
            float go0 = acc[j + 8][rs * 2]     + ax0 * Wx0[64 + col]     + ax1 * Wx1[64 + col]     + bsum[64 + col];
            float go1 = acc[j + 8][rs * 2 + 1] + ax0 * Wx0[64 + col + 1] + ax1 * Wx1[64 + col + 1] + bsum[64 + col + 1];
            float gg0 = acc[j + 12][rs * 2]     + ax0 * Wx0[96 + col]     + ax1 * Wx1[96 + col]     + bsum[96 + col];
            float gg1 = acc[j + 12][rs * 2 + 1] + ax0 * Wx0[96 + col + 1] + ax1 * Wx1[96 + col + 1] + bsum[96 + col + 1];

            float iv0 = fsig(gi0), iv1 = fsig(gi1);
            float fv0 = fsig(gf0), fv1 = fsig(gf1);
            float ov0 = fsig(go0), ov1 = fsig(go1);
            float gv0 = ftanh(gg0), gv1 = ftanh(gg1);

            size_t ci = (size_t)r * 32 + col;
            float2 cold = *(const float2*)&g_C[ci];
            float cn0 = fv0 * cold.x + iv0 * gv0;
            float cn1 = fv1 * cold.y + iv1 * gv1;
            *(float2*)&g_C[ci] = make_float2(cn0, cn1);
            float h0 = ov0 * ftanh(cn0);
            float h1 = ov1 * ftanh(cn1);
            *(__half2*)&g_Rh[(size_t)n * 1024 + b * 32 + col] = __floats2half2_rn(h0, h1);
            if (t == Tt - 1) *(float2*)&g_Hf[ci] = make_float2(h0, h1);
        }
    }
}

// ---------------------------------------------------------------------------
// out[b, hz, n, 0] = sum_k h[b,n,k] * Wp[k,hz] + bp[hz]
// ---------------------------------------------------------------------------
__global__ __launch_bounds__(256) void proj_kernel(const float* __restrict__ Wp,
                                                   const float* __restrict__ bp,
                                                   float* __restrict__ out) {
    int idx = blockIdx.x * 256 + threadIdx.x;
    int n = idx & (Nn - 1);
    int b = idx >> 11;
    float hv[32];
#pragma unroll
    for (int k = 0; k < 32; k++) hv[k] = g_Hf[(size_t)n * 1024 + b * 32 + k];
#pragma unroll
    for (int hz = 0; hz < HOR; hz++) {
        float s = bp[hz];
#pragma unroll
        for (int k = 0; k < 32; k++) s += hv[k] * Wp[k * HOR + hz];
        out[((size_t)b * HOR + hz) * Nn + n] = s;
    }
}

// ---------------------------------------------------------------------------
extern "C" void kernel_launch(void* const* d_in, const int* in_sizes, int n_in,
                              void* d_out, int out_size) {
    const float* x  = (const float*)d_in[0];
    const float* E1 = (const float*)d_in[1];
    const float* E2 = (const float*)d_in[2];
    const float* Wx = (const float*)d_in[3];
    const float* bx = (const float*)d_in[4];
    const float* Wh = (const float*)d_in[5];
    const float* bh = (const float*)d_in[6];
    const float* Wp = (const float*)d_in[7];
    const float* bp = (const float*)d_in[8];
    float* out = (float*)d_out;

    void *pRh, *pC, *pAh, *pG, *pBxh;
    cudaGetSymbolAddress(&pRh, g_Rh);
    cudaGetSymbolAddress(&pC, g_C);
    cudaGetSymbolAddress(&pAh, g_Ah);
    cudaGetSymbolAddress(&pG, g_G);
    cudaGetSymbolAddress(&pBxh, g_Bxh);

    static int smem_set = 0;
    if (!smem_set) {
        cudaFuncSetAttribute(sgemm_fp16, cudaFuncAttributeMaxDynamicSharedMemorySize,
                             3 * SSTAGEH * (int)sizeof(__half));
        smem_set = 1;
    }

    cudaMemsetAsync(pRh, 0, sizeof(__half) * Nn * 1024, 0);
    cudaMemsetAsync(pC, 0, sizeof(float) * Nn * Bb * Hh, 0);

    adj_kernel<<<Nn, 256>>>(E1, E2);
    buildx_kernel<<<(Nn * 1024) / 256, 256>>>(x);

    size_t gemmSmem = 3 * SSTAGEH * sizeof(__half);
    dim3 gemmGrid(1024 / 128, Nn / 128, 2);  // (8, 16, 2) = 256 CTAs

    // Gx = A @ X_all (split halves into g_G, summed into g_Gx)
    sgemm_fp16<<<gemmGrid, 128, gemmSmem>>>((const __half*)pAh, (const __half*)pBxh,
                                            (float*)pG, GSTRIDE);
    addx_kernel<<<GSTRIDE / 256, 256>>>();

    for (int t = 0; t < Tt; t++) {
        sgemm_fp16<<<gemmGrid, 128, gemmSmem>>>((const __half*)pAh, (const __half*)pRh,
                                                (float*)pG, GSTRIDE);
        lstm_tc<<<(Nn * Bb) / 128, 256>>>(Wx, bx, Wh, bh, t);
    }

    proj_kernel<<<(Bb * Nn) / 256, 256>>>(Wp, bp, out);
}

// round 6
// speedup vs baseline: 2.0891x; 1.2471x over previous
#include <cuda_runtime.h>
#include <cuda_fp16.h>
#include <math.h>
#include <stdint.h>

// Problem constants
#define Nn   2048
#define CIN  2
#define Hh   32
#define EMB  16
#define HOR  12
#define Bb   32
#define Tt   16
#define KD   2048
#define GSTRIDE (Nn * 1024)

// Device scratch
__device__ __half g_Ah [Nn * Nn];       // adjacency fp16, [m][k] row-major
__device__ __half g_Rh [Nn * 1024];     // H fp16, [node(k)][b*32+h(n)]
__device__ __half g_Bxh[Nn * 1024];     // X all timesteps fp16
__device__ __half g_Gh [2 * GSTRIDE];   // split-K halves of A @ H, fp16
__device__ float  g_Gx [Nn * 1024];     // A @ X_all (summed, fp32)
__device__ float  g_C  [Nn * Bb * Hh];  // cell state, FRAGMENT layout (lstm-private)
__device__ float  g_Hf [Nn * Bb * Hh];  // fp32 h (normal layout), written at t=15

// ---------------------------------------------------------------------------
__device__ __forceinline__ float fsig(float x) { return 1.0f / (1.0f + __expf(-x)); }
__device__ __forceinline__ float ftanh(float x) { return 2.0f / (1.0f + __expf(-2.0f * x)) - 1.0f; }

__device__ __forceinline__ void cp16(void* dst, const void* src) {
    uint32_t s = (uint32_t)__cvta_generic_to_shared(dst);
    asm volatile("cp.async.cg.shared.global [%0], [%1], 16;" :: "r"(s), "l"(src));
}

__device__ __forceinline__ void ldsm_x4(uint32_t (&r)[4], const void* p) {
    uint32_t a = (uint32_t)__cvta_generic_to_shared(p);
    asm volatile("ldmatrix.sync.aligned.m8n8.x4.shared.b16 {%0,%1,%2,%3}, [%4];"
                 : "=r"(r[0]), "=r"(r[1]), "=r"(r[2]), "=r"(r[3]) : "r"(a));
}
__device__ __forceinline__ void ldsm_x4_t(uint32_t (&r)[4], const void* p) {
    uint32_t a = (uint32_t)__cvta_generic_to_shared(p);
    asm volatile("ldmatrix.sync.aligned.m8n8.x4.trans.shared.b16 {%0,%1,%2,%3}, [%4];"
                 : "=r"(r[0]), "=r"(r[1]), "=r"(r[2]), "=r"(r[3]) : "r"(a));
}

__device__ __forceinline__ void mma_fp16(float (&d)[4], const uint32_t (&a)[4], const uint32_t* b) {
    asm volatile(
        "mma.sync.aligned.m16n8k16.row.col.f32.f16.f16.f32 "
        "{%0,%1,%2,%3}, {%4,%5,%6,%7}, {%8,%9}, {%0,%1,%2,%3};"
        : "+f"(d[0]), "+f"(d[1]), "+f"(d[2]), "+f"(d[3])
        : "r"(a[0]), "r"(a[1]), "r"(a[2]), "r"(a[3]), "r"(b[0]), "r"(b[1]));
}

// ---------------------------------------------------------------------------
// A = softmax(relu(E1 @ E2^T)) row-major [m][k], written as fp16
// ---------------------------------------------------------------------------
__global__ __launch_bounds__(256) void adj_kernel(const float* __restrict__ E1,
                                                  const float* __restrict__ E2) {
    int r = blockIdx.x;
    int tid = threadIdx.x;
    __shared__ float e1[EMB];
    __shared__ float red[256];
    if (tid < EMB) e1[tid] = E1[r * EMB + tid];
    __syncthreads();

    float v[8];
    float mx = -1e30f;
#pragma unroll
    for (int i = 0; i < 8; i++) {
        int c = tid + i * 256;
        float d = 0.f;
#pragma unroll
        for (int e = 0; e < EMB; e++) d += e1[e] * E2[c * EMB + e];
        d = fmaxf(d, 0.f);
        v[i] = d;
        mx = fmaxf(mx, d);
    }
    red[tid] = mx; __syncthreads();
    for (int s = 128; s > 0; s >>= 1) {
        if (tid < s) red[tid] = fmaxf(red[tid], red[tid + s]);
        __syncthreads();
    }
    mx = red[0]; __syncthreads();

    float sum = 0.f;
#pragma unroll
    for (int i = 0; i < 8; i++) { v[i] = expf(v[i] - mx); sum += v[i]; }
    red[tid] = sum; __syncthreads();
    for (int s = 128; s > 0; s >>= 1) {
        if (tid < s) red[tid] += red[tid + s];
        __syncthreads();
    }
    float inv = 1.0f / red[0];
#pragma unroll
    for (int i = 0; i < 8; i++)
        g_Ah[(size_t)r * Nn + tid + i * 256] = __float2half_rn(v[i] * inv);
}

// ---------------------------------------------------------------------------
// g_Bxh[n][t*64 + b*2 + c] = fp16(x[b][t][n][c])
// ---------------------------------------------------------------------------
__global__ __launch_bounds__(256) void buildx_kernel(const float* __restrict__ x) {
    int idx = blockIdx.x * 256 + threadIdx.x;
    int n = idx >> 10;
    int q = idx & 1023;
    int t = q >> 6;
    int r6 = q & 63;
    int b = r6 >> 1;
    int c = r6 & 1;
    g_Bxh[idx] = __float2half_rn(x[(((size_t)b * Tt + t) * Nn + n) * CIN + c]);
}

// g_Gx = (fp32) g_Gh[0..] + g_Gh[GSTRIDE..]   (half2 -> float2)
__global__ __launch_bounds__(256) void addx_kernel() {
    int i = blockIdx.x * 256 + threadIdx.x;   // half2 index
    __half2 a = ((const __half2*)g_Gh)[i];
    __half2 b = ((const __half2*)(g_Gh + GSTRIDE))[i];
    ((float2*)g_Gx)[i] = make_float2(__low2float(a) + __low2float(b),
                                     __high2float(a) + __high2float(b));
}

// ---------------------------------------------------------------------------
// fp16 tensor-core GEMM, split-K: C_z[2048 x 1024] = A[:, z-half] @ B[z-half]
// Output stored as fp16.
// ---------------------------------------------------------------------------
#define APITCH 40
#define BPITCH 136
#define ASZH (128 * APITCH)
#define BSZH (32 * BPITCH)
#define SSTAGEH (ASZH + BSZH)
#define KSPLIT 1024

__global__ void __launch_bounds__(128, 2)
sgemm_fp16(const __half* __restrict__ Ah, const __half* __restrict__ Bh,
           __half* __restrict__ C) {
    extern __shared__ __half smem[];
    int tid = threadIdx.x;
    int lane = tid & 31;
    int w = tid >> 5;
    int bm0 = blockIdx.y * 128;
    int bn0 = blockIdx.x * 128;
    int kBase = blockIdx.z * KSPLIT;
    C += (size_t)blockIdx.z * GSTRIDE;
    int wm0 = (w & 1) * 64;
    int wn0 = (w >> 1) * 64;

    float acc[4][8][4];
#pragma unroll
    for (int mt = 0; mt < 4; mt++)
#pragma unroll
        for (int nt = 0; nt < 8; nt++)
#pragma unroll
            for (int i = 0; i < 4; i++) acc[mt][nt][i] = 0.f;

    auto load_stage = [&](int s, int k0) {
        __half* sA = smem + s * SSTAGEH;
        __half* sB = sA + ASZH;
#pragma unroll
        for (int i = 0; i < 4; i++) {
            int ch = tid + i * 128;
            int r = ch >> 2;
            int c = ch & 3;
            cp16(sA + r * APITCH + c * 8,
                 Ah + (size_t)(bm0 + r) * KD + kBase + k0 + c * 8);
        }
#pragma unroll
        for (int i = 0; i < 4; i++) {
            int ch = tid + i * 128;
            int r = ch >> 4;
            int c = ch & 15;
            cp16(sB + r * BPITCH + c * 8,
                 Bh + (size_t)(kBase + k0 + r) * 1024 + bn0 + c * 8);
        }
    };

    load_stage(0, 0);
    asm volatile("cp.async.commit_group;" ::: "memory");
    load_stage(1, 32);
    asm volatile("cp.async.commit_group;" ::: "memory");

    const int NIT = KSPLIT / 32;
    for (int it = 0; it < NIT; ++it) {
        if (it + 2 < NIT) {
            asm volatile("cp.async.wait_group 1;" ::: "memory");
        } else {
            asm volatile("cp.async.wait_group 0;" ::: "memory");
        }
        __syncthreads();
        if (it + 2 < NIT) {
            load_stage((it + 2) % 3, (it + 2) * 32);
            asm volatile("cp.async.commit_group;" ::: "memory");
        }

        const __half* sA = smem + (it % 3) * SSTAGEH;
        const __half* sB = sA + ASZH;
#pragma unroll
        for (int kk = 0; kk < 2; kk++) {
            uint32_t a[4][4];
#pragma unroll
            for (int mt = 0; mt < 4; mt++) {
                ldsm_x4(a[mt], sA + (wm0 + mt * 16 + (lane & 15)) * APITCH
                               + kk * 16 + ((lane >> 4) << 3));
            }
            uint32_t b[8][2];
#pragma unroll
            for (int np = 0; np < 4; np++) {
                uint32_t t4[4];
                ldsm_x4_t(t4, sB + (kk * 16 + (lane & 15)) * BPITCH
                              + wn0 + np * 16 + ((lane >> 4) << 3));
                b[np * 2][0] = t4[0]; b[np * 2][1] = t4[1];
                b[np * 2 + 1][0] = t4[2]; b[np * 2 + 1][1] = t4[3];
            }
#pragma unroll
            for (int mt = 0; mt < 4; mt++)
#pragma unroll
                for (int nt = 0; nt < 8; nt++) mma_fp16(acc[mt][nt], a[mt], b[nt]);
        }
    }

#pragma unroll
    for (int mt = 0; mt < 4; mt++) {
        int r0 = bm0 + wm0 + mt * 16 + (lane >> 2);
#pragma unroll
        for (int nt = 0; nt < 8; nt++) {
            int c0 = bn0 + wn0 + nt * 8 + 2 * (lane & 3);
            *(__half2*)&C[(size_t)r0 * 1024 + c0] = __floats2half2_rn(acc[mt][nt][0], acc[mt][nt][1]);
            *(__half2*)&C[(size_t)(r0 + 8) * 1024 + c0] = __floats2half2_rn(acc[mt][nt][2], acc[mt][nt][3]);
        }
    }
}

// ---------------------------------------------------------------------------
// LSTM: gates[65536 x 128] = (G0+G1)[65536 x 32] @ Wh[32 x 128], fp16 mma.
// C kept in fragment-linear layout (coalesced). h -> g_Rh (fp16), t=15 -> g_Hf.
// ---------------------------------------------------------------------------
__global__ void __launch_bounds__(256, 2)
lstm_tc(const float* __restrict__ Wx, const float* __restrict__ bx,
        const float* __restrict__ Wh, const float* __restrict__ bh, int t) {
    __shared__ __half Whs[32 * BPITCH];
    __shared__ float Wx0[128], Wx1[128], bsum[128];
    int tid = threadIdx.x;
    for (int i = tid; i < 4096; i += 256) {
        int k = i >> 7, g = i & 127;
        Whs[k * BPITCH + g] = __float2half_rn(Wh[i]);
    }
    if (tid < 128) {
        Wx0[tid] = Wx[tid];
        Wx1[tid] = Wx[128 + tid];
        bsum[tid] = bx[tid] + bh[tid];
    }
    __syncthreads();

    int lane = tid & 31, warp = tid >> 5;
    int rowbase = blockIdx.x * 128 + warp * 16;
    int r_lo = rowbase + (lane >> 2);

    float acc[16][4];
#pragma unroll
    for (int nt = 0; nt < 16; nt++)
#pragma unroll
        for (int i = 0; i < 4; i++) acc[nt][i] = 0.f;

    const __half2* G0 = (const __half2*)g_Gh;
    const __half2* G1 = (const __half2*)(g_Gh + GSTRIDE);

#pragma unroll
    for (int kk = 0; kk < 2; kk++) {
        // A fragments: rows r_lo, r_lo+8; k = kk*16 + (lane&3)*2 (+1, +8)
        int idx = r_lo * 16 + kk * 8 + (lane & 3);   // half2 index
        int idxh = idx + 8 * 16;                     // row +8
        __half2 s0 = __hadd2(G0[idx],      G1[idx]);
        __half2 s1 = __hadd2(G0[idxh],     G1[idxh]);
        __half2 s2 = __hadd2(G0[idx + 4],  G1[idx + 4]);
        __half2 s3 = __hadd2(G0[idxh + 4], G1[idxh + 4]);
        uint32_t a[4];
        a[0] = *reinterpret_cast<uint32_t*>(&s0);
        a[1] = *reinterpret_cast<uint32_t*>(&s1);
        a[2] = *reinterpret_cast<uint32_t*>(&s2);
        a[3] = *reinterpret_cast<uint32_t*>(&s3);

        uint32_t b[16][2];
#pragma unroll
        for (int np = 0; np < 8; np++) {
            uint32_t t4[4];
            ldsm_x4_t(t4, Whs + (kk * 16 + (lane & 15)) * BPITCH
                          + np * 16 + ((lane >> 4) << 3));
            b[np * 2][0] = t4[0]; b[np * 2][1] = t4[1];
            b[np * 2 + 1][0] = t4[2]; b[np * 2 + 1][1] = t4[3];
        }
#pragma unroll
        for (int nt = 0; nt < 16; nt++) mma_fp16(acc[nt], a, b[nt]);
    }

    int cole = 2 * (lane & 3);
    float2* Cp = (float2*)g_C;
#pragma unroll
    for (int rs = 0; rs < 2; rs++) {
        int r = r_lo + rs * 8;
        int n = r >> 5, b = r & 31;
        float2 ax = *(const float2*)&g_Gx[(size_t)n * 1024 + t * 64 + b * 2];
        float ax0 = ax.x, ax1 = ax.y;
#pragma unroll
        for (int j = 0; j < 4; j++) {
            int col = j * 8 + cole;
            float gi0 = acc[j][rs * 2]      + ax0 * Wx0[col]      + ax1 * Wx1[col]      + bsum[col];
            float gi1 = acc[j][rs * 2 + 1]  + ax0 * Wx0[col + 1]  + ax1 * Wx1[col + 1]  + bsum[col + 1];
            float gf0 = acc[j + 4][rs * 2]     + ax0 * Wx0[32 + col]     + ax1 * Wx1[32 + col]     + bsum[32 + col];
            float gf1 = acc[j + 4][rs * 2 + 1] + ax0 * Wx0[32 + col + 1] + ax1 * Wx1[32 + col + 1] + bsum[32 + col + 1];
            float go0 = acc[j + 8][rs * 2]     + ax0 * Wx0[64 + col]     + ax1 * Wx1[64 + col]     + bsum[64 + col];
            float go1 = acc[j + 8][rs * 2 + 1] + ax0 * Wx0[64 + col + 1] + ax1 * Wx1[64 + col + 1] + bsum[64 + col + 1];
            float gg0 = acc[j + 12][rs * 2]     + ax0 * Wx0[96 + col]     + ax1 * Wx1[96 + col]     + bsum[96 + col];
            float gg1 = acc[j + 12][rs * 2 + 1] + ax0 * Wx0[96 + col + 1] + ax1 * Wx1[96 + col + 1] + bsum[96 + col + 1];

            float iv0 = fsig(gi0), iv1 = fsig(gi1);
            float fv0 = fsig(gf0), fv1 = fsig(gf1);
            float ov0 = fsig(go0), ov1 = fsig(go1);
            float gv0 = ftanh(gg0), gv1 = ftanh(gg1);

            // fragment-linear C slot: fully coalesced per warp
            int tslot = ((((blockIdx.x * 8 + warp) * 2 + rs) * 4 + j) << 5) + lane;
            float2 cold = Cp[tslot];
            float cn0 = fv0 * cold.x + iv0 * gv0;
            float cn1 = fv1 * cold.y + iv1 * gv1;
            Cp[tslot] = make_float2(cn0, cn1);
            float h0 = ov0 * ftanh(cn0);
            float h1 = ov1 * ftanh(cn1);
            *(__half2*)&g_Rh[(size_t)n * 1024 + b * 32 + col] = __floats2half2_rn(h0, h1);
            if (t == Tt - 1) *(float2*)&g_Hf[(size_t)r * 32 + col] = make_float2(h0, h1);
        }
    }
}

// ---------------------------------------------------------------------------
// out[b, hz, n, 0] = sum_k h[b,n,k] * Wp[k,hz] + bp[hz]
// ---------------------------------------------------------------------------
__global__ __launch_bounds__(256) void proj_kernel(const float* __restrict__ Wp,
                                                   const float* __restrict__ bp,
                                                   float* __restrict__ out) {
    int idx = blockIdx.x * 256 + threadIdx.x;
    int n = idx & (Nn - 1);
    int b = idx >> 11;
    float hv[32];
#pragma unroll
    for (int k = 0; k < 32; k++) hv[k] = g_Hf[(size_t)n * 1024 + b * 32 + k];
#pragma unroll
    for (int hz = 0; hz < HOR; hz++) {
        float s = bp[hz];
#pragma unroll
        for (int k = 0; k < 32; k++) s += hv[k] * Wp[k * HOR + hz];
        out[((size_t)b * HOR + hz) * Nn + n] = s;
    }
}

// ---------------------------------------------------------------------------
extern "C" void kernel_launch(void* const* d_in, const int* in_sizes, int n_in,
                              void* d_out, int out_size) {
    const float* x  = (const float*)d_in[0];
    const float* E1 = (const float*)d_in[1];
    const float* E2 = (const float*)d_in[2];
    const float* Wx = (const float*)d_in[3];
    const float* bx = (const float*)d_in[4];
    const float* Wh = (const float*)d_in[5];
    const float* bh = (const float*)d_in[6];
    const float* Wp = (const float*)d_in[7];
    const float* bp = (const float*)d_in[8];
    float* out = (float*)d_out;

    void *pRh, *pC, *pAh, *pGh, *pBxh;
    cudaGetSymbolAddress(&pRh, g_Rh);
    cudaGetSymbolAddress(&pC, g_C);
    cudaGetSymbolAddress(&pAh, g_Ah);
    cudaGetSymbolAddress(&pGh, g_Gh);
    cudaGetSymbolAddress(&pBxh, g_Bxh);

    static int smem_set = 0;
    if (!smem_set) {
        cudaFuncSetAttribute(sgemm_fp16, cudaFuncAttributeMaxDynamicSharedMemorySize,
                             3 * SSTAGEH * (int)sizeof(__half));
        smem_set = 1;
    }

    cudaMemsetAsync(pRh, 0, sizeof(__half) * Nn * 1024, 0);
    cudaMemsetAsync(pC, 0, sizeof(float) * Nn * Bb * Hh, 0);

    adj_kernel<<<Nn, 256>>>(E1, E2);
    buildx_kernel<<<(Nn * 1024) / 256, 256>>>(x);

    size_t gemmSmem = 3 * SSTAGEH * sizeof(__half);
    dim3 gemmGrid(1024 / 128, Nn / 128, 2);  // (8, 16, 2) = 256 CTAs

    // Gx = A @ X_all
    sgemm_fp16<<<gemmGrid, 128, gemmSmem>>>((const __half*)pAh, (const __half*)pBxh,
                                            (__half*)pGh);
    addx_kernel<<<GSTRIDE / 512, 256>>>();

    for (int t = 0; t < Tt; t++) {
        sgemm_fp16<<<gemmGrid, 128, gemmSmem>>>((const __half*)pAh, (const __half*)pRh,
                                                (__half*)pGh);
        lstm_tc<<<(Nn * Bb) / 128, 256>>>(Wx, bx, Wh, bh, t);
    }

    proj_kernel<<<(Bb * Nn) / 256, 256>>>(Wp, bp, out);
}